// round 5
// baseline (speedup 1.0000x reference)
#include <cuda_runtime.h>
#include <cstdint>

#define N_NODES 50000
#define N_EDGES 800000
#define D 96

// ---------------- scratch (static device allocations are allowed) ----------------
__device__ int   g_is64;                    // 1 if rows/cols are int64
__device__ int   g_counts[N_NODES];
__device__ int   g_cursor[N_NODES];
__device__ int   g_row_ptr[N_NODES + 1];
__device__ int2  g_edges[N_EDGES];          // {col, val bits}
__device__ float g_Y [N_NODES * D];         // T0' = H @ W
__device__ float g_T1[N_NODES * D];
__device__ float g_T2[N_NODES * D];

// ---------------- index dtype probe ----------------
// If rows is int64 (values < 2^31, nonnegative), every odd int32 word of the
// buffer is zero. If int32, odd words are random indices in [0, 50000) and
// the OR over 100k of them is nonzero with overwhelming probability.
__global__ void detect_kernel(const int* __restrict__ rows) {
    __shared__ int any;
    if (threadIdx.x == 0) any = 0;
    __syncthreads();
    int acc = 0;
    for (int i = 2 * threadIdx.x + 1; i < 200000; i += 2 * blockDim.x)
        acc |= rows[i];
    if (acc) atomicOr(&any, 1);
    __syncthreads();
    if (threadIdx.x == 0) g_is64 = any ? 0 : 1;
}

__device__ __forceinline__ int load_idx(const int* __restrict__ p, int i, int is64) {
    return is64 ? p[2 * i] : p[i];   // little-endian low word of int64
}

// ---------------- CSR build ----------------
__global__ void zero_kernel() {
    int i = blockIdx.x * blockDim.x + threadIdx.x;
    int stride = gridDim.x * blockDim.x;
    for (; i < N_NODES; i += stride) { g_counts[i] = 0; g_cursor[i] = 0; }
}

__global__ void hist_kernel(const int* __restrict__ rows) {
    const int is64 = g_is64;
    int i = blockIdx.x * blockDim.x + threadIdx.x;
    int stride = gridDim.x * blockDim.x;
    for (; i < N_EDGES; i += stride) atomicAdd(&g_counts[load_idx(rows, i, is64)], 1);
}

// single-block exclusive scan of g_counts -> g_row_ptr
__global__ void scan_kernel() {
    __shared__ int partial[1024];
    const int tid = threadIdx.x;
    const int CH = (N_NODES + 1023) / 1024;   // 49
    int begin = tid * CH;
    int endi  = begin + CH; if (endi > N_NODES) endi = N_NODES;
    if (begin > N_NODES) begin = N_NODES;
    int s = 0;
    for (int i = begin; i < endi; i++) s += g_counts[i];
    partial[tid] = s;
    __syncthreads();
    for (int off = 1; off < 1024; off <<= 1) {
        int v = (tid >= off) ? partial[tid - off] : 0;
        __syncthreads();
        partial[tid] += v;
        __syncthreads();
    }
    int run = partial[tid] - s;   // exclusive base for this chunk
    for (int i = begin; i < endi; i++) {
        g_row_ptr[i] = run;
        run += g_counts[i];
    }
    if (tid == 1023) g_row_ptr[N_NODES] = partial[1023];
}

__global__ void scatter_kernel(const int* __restrict__ rows,
                               const int* __restrict__ cols,
                               const float* __restrict__ vals) {
    const int is64 = g_is64;
    int i = blockIdx.x * blockDim.x + threadIdx.x;
    int stride = gridDim.x * blockDim.x;
    for (; i < N_EDGES; i += stride) {
        int r = load_idx(rows, i, is64);
        int pos = g_row_ptr[r] + atomicAdd(&g_cursor[r], 1);
        g_edges[pos] = make_int2(load_idx(cols, i, is64), __float_as_int(vals[i]));
    }
}

// ---------------- GEMM: Y = H @ W ; out = Y ----------------
// blockDim = (96, 4) = 384 threads; each block handles 16 rows (4 rows/thread)
#define GEMM_RPB 16
__global__ __launch_bounds__(384) void gemm_kernel(const float* __restrict__ H,
                                                   const float* __restrict__ W,
                                                   float* __restrict__ out) {
    __shared__ float Ws[D * D];
    __shared__ float Hs[GEMM_RPB][D];
    const int tid = threadIdx.y * 96 + threadIdx.x;
    for (int i = tid; i < D * D; i += 384) Ws[i] = W[i];
    const int row0 = blockIdx.x * GEMM_RPB;
    for (int i = tid; i < GEMM_RPB * D; i += 384) {
        int r = i / D, c = i % D;
        int gr = row0 + r;
        Hs[r][c] = (gr < N_NODES) ? H[gr * D + c] : 0.0f;
    }
    __syncthreads();
    const int j = threadIdx.x;
    const int rbase = threadIdx.y * 4;
    float acc0 = 0.f, acc1 = 0.f, acc2 = 0.f, acc3 = 0.f;
    #pragma unroll 8
    for (int k = 0; k < D; k++) {
        float w = Ws[k * D + j];
        acc0 = fmaf(Hs[rbase + 0][k], w, acc0);
        acc1 = fmaf(Hs[rbase + 1][k], w, acc1);
        acc2 = fmaf(Hs[rbase + 2][k], w, acc2);
        acc3 = fmaf(Hs[rbase + 3][k], w, acc3);
    }
    float accs[4] = {acc0, acc1, acc2, acc3};
    #pragma unroll
    for (int i = 0; i < 4; i++) {
        int r = row0 + rbase + i;
        if (r < N_NODES) {
            float v = accs[i];
            g_Y[r * D + j] = v;   // device-side symbol reference: valid
            out[r * D + j] = v;
        }
    }
}

// ---------------- fused SpMM + Chebyshev step ----------------
// One warp per row. lane owns features {lane, lane+32, lane+64}.
// t = a * spmm(X)[r] + b * X[r] + c * P[r]    (P optional)
// Tout[r] = t (optional);  out[r] += t (+ bias, optional)
__global__ __launch_bounds__(256) void spmm_kernel(const float* __restrict__ X,
                                                   const float* __restrict__ P,
                                                   float* __restrict__ Tout,
                                                   float* __restrict__ out,
                                                   const float* __restrict__ bias,
                                                   float a, float b, float c) {
    const int w = (blockIdx.x * blockDim.x + threadIdx.x) >> 5;
    if (w >= N_NODES) return;
    const int lane = threadIdx.x & 31;
    const int start = g_row_ptr[w];
    const int end   = g_row_ptr[w + 1];

    float a0 = 0.f, a1 = 0.f, a2 = 0.f;
    #pragma unroll 4
    for (int e = start; e < end; ++e) {
        int2 ed = g_edges[e];                         // warp-uniform broadcast
        const float* xr = X + (size_t)ed.x * D + lane;
        float v = __int_as_float(ed.y);
        a0 = fmaf(v, __ldg(xr),      a0);
        a1 = fmaf(v, __ldg(xr + 32), a1);
        a2 = fmaf(v, __ldg(xr + 64), a2);
    }

    const size_t base = (size_t)w * D + lane;
    float t0 = a * a0 + b * X[base];
    float t1 = a * a1 + b * X[base + 32];
    float t2 = a * a2 + b * X[base + 64];
    if (P) {
        t0 += c * P[base];
        t1 += c * P[base + 32];
        t2 += c * P[base + 64];
    }
    if (Tout) {
        Tout[base]      = t0;
        Tout[base + 32] = t1;
        Tout[base + 64] = t2;
    }
    float o0 = out[base]      + t0;
    float o1 = out[base + 32] + t1;
    float o2 = out[base + 64] + t2;
    if (bias) {
        o0 += bias[lane];
        o1 += bias[lane + 32];
        o2 += bias[lane + 64];
    }
    out[base]      = o0;
    out[base + 32] = o1;
    out[base + 64] = o2;
}

// ---------------- launch ----------------
extern "C" void kernel_launch(void* const* d_in, const int* in_sizes, int n_in,
                              void* d_out, int out_size) {
    const int*   rows = (const int*)  d_in[0];
    const int*   cols = (const int*)  d_in[1];
    const float* vals = (const float*)d_in[2];
    const float* H    = (const float*)d_in[3];
    const float* W    = (const float*)d_in[4];
    const float* bias = (const float*)d_in[5];
    float* out = (float*)d_out;

    // Real DEVICE addresses of the scratch symbols (host-side symbol names are
    // shadow addresses — passing them as kernel args was the R2/R4 bug).
    // cudaGetSymbolAddress is a capture-safe query, not an allocation.
    float *Yp = nullptr, *T1p = nullptr, *T2p = nullptr;
    cudaGetSymbolAddress((void**)&Yp,  g_Y);
    cudaGetSymbolAddress((void**)&T1p, g_T1);
    cudaGetSymbolAddress((void**)&T2p, g_T2);

    // index dtype probe + CSR build (every call — no caching)
    detect_kernel<<<1, 256>>>(rows);
    zero_kernel<<<256, 256>>>();
    hist_kernel<<<1024, 256>>>(rows);
    scan_kernel<<<1, 1024>>>();
    scatter_kernel<<<1024, 256>>>(rows, cols, vals);

    // Y = H @ W ; out = Y
    dim3 gblk(96, 4);
    gemm_kernel<<<(N_NODES + GEMM_RPB - 1) / GEMM_RPB, gblk>>>(H, W, out);

    const int SPMM_BLOCKS = (N_NODES * 32 + 255) / 256;
    // T1 = 2*spmm(Y) - Y ; out += T1
    spmm_kernel<<<SPMM_BLOCKS, 256>>>(Yp,  nullptr, T1p, out, nullptr, 2.f, -1.f, 0.f);
    // T2 = 4*spmm(T1) - 2*T1 - Y ; out += T2
    spmm_kernel<<<SPMM_BLOCKS, 256>>>(T1p, Yp,      T2p, out, nullptr, 4.f, -2.f, -1.f);
    // T3 = 4*spmm(T2) - 2*T2 - T1 ; out += T3 + bias
    spmm_kernel<<<SPMM_BLOCKS, 256>>>(T2p, T1p, nullptr, out, bias,    4.f, -2.f, -1.f);
}

// round 6
// speedup vs baseline: 1.3506x; 1.3506x over previous
#include <cuda_runtime.h>
#include <cstdint>

#define N_NODES 50000
#define N_EDGES 800000
#define D 96
#define D4 (D / 4)            // 24 float4 per row

// ---------------- scratch ----------------
__device__ int    g_is64;
__device__ int    g_counts[N_NODES];
__device__ int    g_cursor[N_NODES];            // running write cursor (starts at row_ptr)
__device__ int    g_row_ptr[N_NODES + 1];
__device__ int    g_bsum[256];
__device__ int    g_bsum_ex[256];
__device__ int2   g_edges[N_EDGES];             // {col, val bits}
__device__ float4 g_Y [N_NODES * D4];           // T0' = H @ W
__device__ float4 g_T1[N_NODES * D4];
__device__ float4 g_T2[N_NODES * D4];

// ---------------- index dtype probe ----------------
// int64 indices < 2^31: every odd int32 word is zero. int32: odd words are
// random indices; OR over 10k of them is nonzero w.p. 1 - (1/50000)^10000.
__global__ void detect_kernel(const int* __restrict__ rows) {
    __shared__ int any;
    if (threadIdx.x == 0) any = 0;
    __syncthreads();
    int acc = 0;
    for (int i = 2 * threadIdx.x + 1; i < 20000; i += 2 * blockDim.x)
        acc |= rows[i];
    if (acc) atomicOr(&any, 1);
    __syncthreads();
    if (threadIdx.x == 0) g_is64 = any ? 0 : 1;
}

__device__ __forceinline__ int load_idx(const int* __restrict__ p, int i, int is64) {
    return is64 ? p[2 * i] : p[i];
}

// ---------------- CSR build ----------------
__global__ void zero_kernel() {
    int i = blockIdx.x * blockDim.x + threadIdx.x;
    int stride = gridDim.x * blockDim.x;
    for (; i < N_NODES; i += stride) g_counts[i] = 0;
}

__global__ void hist_kernel(const int* __restrict__ rows) {
    const int is64 = g_is64;
    int i = blockIdx.x * blockDim.x + threadIdx.x;
    int stride = gridDim.x * blockDim.x;
    for (; i < N_EDGES; i += stride) atomicAdd(&g_counts[load_idx(rows, i, is64)], 1);
}

// --- three-phase scan: counts -> row_ptr (exclusive), cursor = row_ptr ---
#define SCAN_BLOCKS 196          // 196*256 = 50176 >= N_NODES
__global__ void scan_phase1() {  // per-block sums
    __shared__ int sm[256];
    int i = blockIdx.x * 256 + threadIdx.x;
    int v = (i < N_NODES) ? g_counts[i] : 0;
    sm[threadIdx.x] = v;
    __syncthreads();
    for (int off = 128; off > 0; off >>= 1) {
        if (threadIdx.x < off) sm[threadIdx.x] += sm[threadIdx.x + off];
        __syncthreads();
    }
    if (threadIdx.x == 0) g_bsum[blockIdx.x] = sm[0];
}

__global__ void scan_phase2() {  // 1 block scans 196 block sums
    __shared__ int sm[256];
    int t = threadIdx.x;
    int v = (t < SCAN_BLOCKS) ? g_bsum[t] : 0;
    sm[t] = v;
    __syncthreads();
    for (int off = 1; off < 256; off <<= 1) {
        int u = (t >= off) ? sm[t - off] : 0;
        __syncthreads();
        sm[t] += u;
        __syncthreads();
    }
    g_bsum_ex[t] = sm[t] - v;    // exclusive
    if (t == 0) g_row_ptr[N_NODES] = N_EDGES;
}

__global__ void scan_phase3() {  // in-block exclusive scan + block offset
    __shared__ int sm[256];
    int t = threadIdx.x;
    int i = blockIdx.x * 256 + t;
    int v = (i < N_NODES) ? g_counts[i] : 0;
    sm[t] = v;
    __syncthreads();
    for (int off = 1; off < 256; off <<= 1) {
        int u = (t >= off) ? sm[t - off] : 0;
        __syncthreads();
        sm[t] += u;
        __syncthreads();
    }
    if (i < N_NODES) {
        int p = g_bsum_ex[blockIdx.x] + sm[t] - v;
        g_row_ptr[i] = p;
        g_cursor[i]  = p;
    }
}

__global__ void scatter_kernel(const int* __restrict__ rows,
                               const int* __restrict__ cols,
                               const float* __restrict__ vals) {
    const int is64 = g_is64;
    int i = blockIdx.x * blockDim.x + threadIdx.x;
    int stride = gridDim.x * blockDim.x;
    for (; i < N_EDGES; i += stride) {
        int r = load_idx(rows, i, is64);
        int pos = atomicAdd(&g_cursor[r], 1);
        g_edges[pos] = make_int2(load_idx(cols, i, is64), __float_as_int(vals[i]));
    }
}

// ---------------- GEMM: Y = H @ W ; out = Y ----------------
#define GEMM_RPB 16
__global__ __launch_bounds__(384) void gemm_kernel(const float* __restrict__ H,
                                                   const float* __restrict__ W,
                                                   float* __restrict__ out) {
    __shared__ float Ws[D * D];
    __shared__ float Hs[GEMM_RPB][D];
    const int tid = threadIdx.y * 96 + threadIdx.x;
    for (int i = tid; i < D * D; i += 384) Ws[i] = W[i];
    const int row0 = blockIdx.x * GEMM_RPB;
    for (int i = tid; i < GEMM_RPB * D; i += 384) {
        int r = i / D, c = i % D;
        int gr = row0 + r;
        Hs[r][c] = (gr < N_NODES) ? H[gr * D + c] : 0.0f;
    }
    __syncthreads();
    const int j = threadIdx.x;
    const int rbase = threadIdx.y * 4;
    float acc0 = 0.f, acc1 = 0.f, acc2 = 0.f, acc3 = 0.f;
    #pragma unroll 8
    for (int k = 0; k < D; k++) {
        float w = Ws[k * D + j];
        acc0 = fmaf(Hs[rbase + 0][k], w, acc0);
        acc1 = fmaf(Hs[rbase + 1][k], w, acc1);
        acc2 = fmaf(Hs[rbase + 2][k], w, acc2);
        acc3 = fmaf(Hs[rbase + 3][k], w, acc3);
    }
    float accs[4] = {acc0, acc1, acc2, acc3};
    float* Yf = (float*)g_Y;       // device-side symbol reference: valid
    #pragma unroll
    for (int i = 0; i < 4; i++) {
        int r = row0 + rbase + i;
        if (r < N_NODES) {
            float v = accs[i];
            Yf[r * D + j]  = v;
            out[r * D + j] = v;
        }
    }
}

// ---------------- fused SpMM + Chebyshev step (float4 lanes) ----------------
// One warp per row; lanes 0..23 each own one float4 (features 4l..4l+3).
// t = a*spmm(X)[r] + b*X[r] + c*P[r];  Tout[r]=t (opt);  out[r] += t (+bias opt)
__global__ __launch_bounds__(256) void spmm_kernel(const float4* __restrict__ X,
                                                   const float4* __restrict__ P,
                                                   float4* __restrict__ Tout,
                                                   float4* __restrict__ out,
                                                   const float4* __restrict__ bias,
                                                   float a, float b, float c) {
    const int w = (blockIdx.x * blockDim.x + threadIdx.x) >> 5;
    if (w >= N_NODES) return;
    const int lane = threadIdx.x & 31;
    if (lane >= D4) return;
    const int start = g_row_ptr[w];
    const int end   = g_row_ptr[w + 1];

    float ax = 0.f, ay = 0.f, az = 0.f, aw = 0.f;
    #pragma unroll 4
    for (int e = start; e < end; ++e) {
        int2 ed = g_edges[e];                      // warp-uniform broadcast
        float v = __int_as_float(ed.y);
        float4 x = __ldg(&X[ed.x * D4 + lane]);
        ax = fmaf(v, x.x, ax);
        ay = fmaf(v, x.y, ay);
        az = fmaf(v, x.z, az);
        aw = fmaf(v, x.w, aw);
    }

    const int base = w * D4 + lane;
    float4 xs = X[base];
    float4 t;
    t.x = a * ax + b * xs.x;
    t.y = a * ay + b * xs.y;
    t.z = a * az + b * xs.z;
    t.w = a * aw + b * xs.w;
    if (P) {
        float4 p = P[base];
        t.x += c * p.x; t.y += c * p.y; t.z += c * p.z; t.w += c * p.w;
    }
    if (Tout) Tout[base] = t;
    float4 o = out[base];
    o.x += t.x; o.y += t.y; o.z += t.z; o.w += t.w;
    if (bias) {
        float4 bv = bias[lane];
        o.x += bv.x; o.y += bv.y; o.z += bv.z; o.w += bv.w;
    }
    out[base] = o;
}

// ---------------- launch ----------------
extern "C" void kernel_launch(void* const* d_in, const int* in_sizes, int n_in,
                              void* d_out, int out_size) {
    const int*   rows = (const int*)  d_in[0];
    const int*   cols = (const int*)  d_in[1];
    const float* vals = (const float*)d_in[2];
    const float* H    = (const float*)d_in[3];
    const float* W    = (const float*)d_in[4];
    const float* bias = (const float*)d_in[5];
    float* out = (float*)d_out;

    // Real DEVICE addresses (host-side symbol names are shadow addresses).
    float4 *Yp = nullptr, *T1p = nullptr, *T2p = nullptr;
    cudaGetSymbolAddress((void**)&Yp,  g_Y);
    cudaGetSymbolAddress((void**)&T1p, g_T1);
    cudaGetSymbolAddress((void**)&T2p, g_T2);

    // probe + CSR build (every call — no caching)
    detect_kernel<<<1, 256>>>(rows);
    zero_kernel<<<256, 256>>>();
    hist_kernel<<<1024, 256>>>(rows);
    scan_phase1<<<SCAN_BLOCKS, 256>>>();
    scan_phase2<<<1, 256>>>();
    scan_phase3<<<SCAN_BLOCKS, 256>>>();
    scatter_kernel<<<1024, 256>>>(rows, cols, vals);

    // Y = H @ W ; out = Y
    dim3 gblk(96, 4);
    gemm_kernel<<<(N_NODES + GEMM_RPB - 1) / GEMM_RPB, gblk>>>(H, W, out);

    const int SPMM_BLOCKS = (N_NODES * 32 + 255) / 256;
    float4* out4 = (float4*)out;
    const float4* bias4 = (const float4*)bias;
    // T1 = 2*spmm(Y) - Y ; out += T1
    spmm_kernel<<<SPMM_BLOCKS, 256>>>(Yp,  nullptr, T1p, out4, nullptr, 2.f, -1.f, 0.f);
    // T2 = 4*spmm(T1) - 2*T1 - Y ; out += T2
    spmm_kernel<<<SPMM_BLOCKS, 256>>>(T1p, Yp,      T2p, out4, nullptr, 4.f, -2.f, -1.f);
    // T3 = 4*spmm(T2) - 2*T2 - T1 ; out += T3 + bias
    spmm_kernel<<<SPMM_BLOCKS, 256>>>(T2p, T1p, nullptr, out4, bias4,   4.f, -2.f, -1.f);
}

// round 7
// speedup vs baseline: 1.4675x; 1.0866x over previous
#include <cuda_runtime.h>
#include <cstdint>

#define N_NODES 50000
#define N_EDGES 800000
#define D 96
#define D4 (D / 4)            // 24 float4 per row

// ---------------- scratch ----------------
__device__ int    g_is64;
__device__ int    g_counts[N_NODES];
__device__ int    g_cursor[N_NODES];            // running write cursor (starts at row_ptr)
__device__ int    g_row_ptr[N_NODES + 1];
__device__ int    g_bsum[256];
__device__ int    g_bsum_ex[256];
__device__ int2   g_edges[N_EDGES];             // {col, val bits}
__device__ float4 g_Y [N_NODES * D4];           // Y = H @ W
__device__ float4 g_T1[N_NODES * D4];
__device__ float4 g_T2[N_NODES * D4];

__device__ __forceinline__ int load_idx(const int* __restrict__ p, int i, int is64) {
    return is64 ? p[2 * i] : p[i];   // little-endian low word of int64
}

// ---------------- fused: zero counts + index-dtype probe ----------------
// int64 indices < 2^31: every odd int32 word is zero. int32: odd words are
// random indices; OR over 10k odd words is nonzero w.p. ~1.
__global__ void zero_detect_kernel(const int* __restrict__ rows) {
    int i = blockIdx.x * blockDim.x + threadIdx.x;
    int stride = gridDim.x * blockDim.x;
    for (; i < N_NODES; i += stride) g_counts[i] = 0;
    if (blockIdx.x == 0) {
        __shared__ int any;
        if (threadIdx.x == 0) any = 0;
        __syncthreads();
        int acc = 0;
        for (int k = 2 * threadIdx.x + 1; k < 20000; k += 2 * blockDim.x)
            acc |= rows[k];
        if (acc) atomicOr(&any, 1);
        __syncthreads();
        if (threadIdx.x == 0) g_is64 = any ? 0 : 1;
    }
}

__global__ void hist_kernel(const int* __restrict__ rows) {
    const int is64 = g_is64;
    int i = blockIdx.x * blockDim.x + threadIdx.x;
    int stride = gridDim.x * blockDim.x;
    for (; i < N_EDGES; i += stride) atomicAdd(&g_counts[load_idx(rows, i, is64)], 1);
}

// --- three-phase scan: counts -> row_ptr (exclusive), cursor = row_ptr ---
#define SCAN_BLOCKS 196          // 196*256 = 50176 >= N_NODES
__global__ void scan_phase1() {
    __shared__ int sm[256];
    int i = blockIdx.x * 256 + threadIdx.x;
    int v = (i < N_NODES) ? g_counts[i] : 0;
    sm[threadIdx.x] = v;
    __syncthreads();
    for (int off = 128; off > 0; off >>= 1) {
        if (threadIdx.x < off) sm[threadIdx.x] += sm[threadIdx.x + off];
        __syncthreads();
    }
    if (threadIdx.x == 0) g_bsum[blockIdx.x] = sm[0];
}

__global__ void scan_phase2() {
    __shared__ int sm[256];
    int t = threadIdx.x;
    int v = (t < SCAN_BLOCKS) ? g_bsum[t] : 0;
    sm[t] = v;
    __syncthreads();
    for (int off = 1; off < 256; off <<= 1) {
        int u = (t >= off) ? sm[t - off] : 0;
        __syncthreads();
        sm[t] += u;
        __syncthreads();
    }
    g_bsum_ex[t] = sm[t] - v;    // exclusive
    if (t == 0) g_row_ptr[N_NODES] = N_EDGES;
}

__global__ void scan_phase3() {
    __shared__ int sm[256];
    int t = threadIdx.x;
    int i = blockIdx.x * 256 + t;
    int v = (i < N_NODES) ? g_counts[i] : 0;
    sm[t] = v;
    __syncthreads();
    for (int off = 1; off < 256; off <<= 1) {
        int u = (t >= off) ? sm[t - off] : 0;
        __syncthreads();
        sm[t] += u;
        __syncthreads();
    }
    if (i < N_NODES) {
        int p = g_bsum_ex[blockIdx.x] + sm[t] - v;
        g_row_ptr[i] = p;
        g_cursor[i]  = p;
    }
}

// ---------------- fused scatter + GEMM (independent work, one launch) ----
// blocks [0, GEMM_BLOCKS): Y = H @ W  (16 rows per block, 384 threads)
// blocks [GEMM_BLOCKS, +SCATTER_BLOCKS): CSR scatter of edges
#define GEMM_RPB 16
#define GEMM_BLOCKS (N_NODES / GEMM_RPB)     // 3125
#define SCATTER_BLOCKS 1024
__global__ __launch_bounds__(384) void scatter_gemm_kernel(
        const int* __restrict__ rows, const int* __restrict__ cols,
        const float* __restrict__ vals,
        const float* __restrict__ H, const float* __restrict__ W) {
    if (blockIdx.x < GEMM_BLOCKS) {
        __shared__ float Ws[D * D];
        __shared__ float Hs[GEMM_RPB][D];
        const int tid = threadIdx.x;
        for (int i = tid; i < D * D; i += 384) Ws[i] = W[i];
        const int row0 = blockIdx.x * GEMM_RPB;
        for (int i = tid; i < GEMM_RPB * D; i += 384) {
            int r = i / D, c = i % D;
            Hs[r][c] = H[(row0 + r) * D + c];
        }
        __syncthreads();
        const int j = tid % 96;
        const int rbase = (tid / 96) * 4;
        float acc0 = 0.f, acc1 = 0.f, acc2 = 0.f, acc3 = 0.f;
        #pragma unroll 8
        for (int k = 0; k < D; k++) {
            float w = Ws[k * D + j];
            acc0 = fmaf(Hs[rbase + 0][k], w, acc0);
            acc1 = fmaf(Hs[rbase + 1][k], w, acc1);
            acc2 = fmaf(Hs[rbase + 2][k], w, acc2);
            acc3 = fmaf(Hs[rbase + 3][k], w, acc3);
        }
        float accs[4] = {acc0, acc1, acc2, acc3};
        float* Yf = (float*)g_Y;               // device-side symbol ref: valid
        #pragma unroll
        for (int i = 0; i < 4; i++)
            Yf[(row0 + rbase + i) * D + j] = accs[i];
    } else {
        const int is64 = g_is64;
        int i = (blockIdx.x - GEMM_BLOCKS) * blockDim.x + threadIdx.x;
        int stride = SCATTER_BLOCKS * blockDim.x;
        for (; i < N_EDGES; i += stride) {
            int r = load_idx(rows, i, is64);
            int pos = atomicAdd(&g_cursor[r], 1);
            g_edges[pos] = make_int2(load_idx(cols, i, is64), __float_as_int(vals[i]));
        }
    }
}

// ---------------- SpMM + Chebyshev combine (float4 lanes) -----------------
// One warp per row; lanes 0..23 own one float4 each.
// O[r] = a*spmm(X)[r] + b*X[r] + c*P[r] (+ bias)
__global__ __launch_bounds__(256) void spmm_kernel(const float4* __restrict__ X,
                                                   const float4* __restrict__ P,
                                                   float4* __restrict__ O,
                                                   const float4* __restrict__ bias,
                                                   float a, float b, float c) {
    const int w = (blockIdx.x * blockDim.x + threadIdx.x) >> 5;
    if (w >= N_NODES) return;
    const int lane = threadIdx.x & 31;
    if (lane >= D4) return;
    const int start = g_row_ptr[w];
    const int end   = g_row_ptr[w + 1];

    float ax = 0.f, ay = 0.f, az = 0.f, aw = 0.f;
    #pragma unroll 4
    for (int e = start; e < end; ++e) {
        int2 ed = g_edges[e];                      // warp-uniform broadcast
        float v = __int_as_float(ed.y);
        float4 x = __ldg(&X[ed.x * D4 + lane]);
        ax = fmaf(v, x.x, ax);
        ay = fmaf(v, x.y, ay);
        az = fmaf(v, x.z, az);
        aw = fmaf(v, x.w, aw);
    }

    const int base = w * D4 + lane;
    float4 xs = X[base];
    float4 t;
    t.x = a * ax + b * xs.x;
    t.y = a * ay + b * xs.y;
    t.z = a * az + b * xs.z;
    t.w = a * aw + b * xs.w;
    if (P) {
        float4 p = P[base];
        t.x += c * p.x; t.y += c * p.y; t.z += c * p.z; t.w += c * p.w;
    }
    if (bias) {
        float4 bv = bias[lane];
        t.x += bv.x; t.y += bv.y; t.z += bv.z; t.w += bv.w;
    }
    O[base] = t;
}

// ---------------- launch ----------------
extern "C" void kernel_launch(void* const* d_in, const int* in_sizes, int n_in,
                              void* d_out, int out_size) {
    const int*   rows = (const int*)  d_in[0];
    const int*   cols = (const int*)  d_in[1];
    const float* vals = (const float*)d_in[2];
    const float* H    = (const float*)d_in[3];
    const float* W    = (const float*)d_in[4];
    const float* bias = (const float*)d_in[5];
    float* out = (float*)d_out;

    // Real DEVICE addresses (host-side symbol names are shadow addresses).
    float4 *Yp = nullptr, *T1p = nullptr, *T2p = nullptr;
    cudaGetSymbolAddress((void**)&Yp,  g_Y);
    cudaGetSymbolAddress((void**)&T1p, g_T1);
    cudaGetSymbolAddress((void**)&T2p, g_T2);

    // CSR build + GEMM (every call — no caching)
    zero_detect_kernel<<<256, 256>>>(rows);
    hist_kernel<<<1024, 256>>>(rows);
    scan_phase1<<<SCAN_BLOCKS, 256>>>();
    scan_phase2<<<1, 256>>>();
    scan_phase3<<<SCAN_BLOCKS, 256>>>();
    scatter_gemm_kernel<<<GEMM_BLOCKS + SCATTER_BLOCKS, 384>>>(rows, cols, vals, H, W);

    const int SPMM_BLOCKS = (N_NODES * 32 + 255) / 256;
    float4* out4 = (float4*)out;
    const float4* bias4 = (const float4*)bias;
    // T1 = 2*S(Y) - Y
    spmm_kernel<<<SPMM_BLOCKS, 256>>>(Yp,  nullptr, T1p, nullptr, 2.f, -1.f, 0.f);
    // T2 = 4*S(T1) - 2*T1 - Y
    spmm_kernel<<<SPMM_BLOCKS, 256>>>(T1p, Yp,      T2p, nullptr, 4.f, -2.f, -1.f);
    // out = Y + T1 + T2 + T3 + bias  ==  4*S(T2) - T2 + Y + bias   (T1 cancels)
    spmm_kernel<<<SPMM_BLOCKS, 256>>>(T2p, Yp,      out4, bias4,   4.f, -1.f,  1.f);
}

// round 8
// speedup vs baseline: 1.5252x; 1.0393x over previous
#include <cuda_runtime.h>
#include <cuda_fp16.h>
#include <cstdint>

#define N_NODES 50000
#define N_EDGES 800000
#define D 96
#define D4 (D / 4)            // 24 float4 (or uint2-of-half) chunks per row

// ---------------- scratch ----------------
__device__ int    g_is64;
__device__ int    g_counts[N_NODES];
__device__ int    g_cursor[N_NODES];
__device__ int    g_row_ptr[N_NODES + 1];
__device__ int    g_bsum[256];
__device__ int2   g_edges[N_EDGES];             // {col, val bits}
__device__ float4 g_Y  [N_NODES * D4];          // fp32 Y = H @ W
__device__ float4 g_T1 [N_NODES * D4];
__device__ float4 g_T2 [N_NODES * D4];
__device__ uint2  g_Yh [N_NODES * D4];          // fp16 shadows (gather operands)
__device__ uint2  g_T1h[N_NODES * D4];
__device__ uint2  g_T2h[N_NODES * D4];

__device__ __forceinline__ int load_idx(const int* __restrict__ p, int i, int is64) {
    return is64 ? p[2 * i] : p[i];   // little-endian low word of int64
}

// ---------------- fused: zero counts + index-dtype probe ----------------
__global__ void zero_detect_kernel(const int* __restrict__ rows) {
    int i = blockIdx.x * blockDim.x + threadIdx.x;
    int stride = gridDim.x * blockDim.x;
    for (; i < N_NODES; i += stride) g_counts[i] = 0;
    if (blockIdx.x == 0) {
        __shared__ int any;
        if (threadIdx.x == 0) any = 0;
        __syncthreads();
        int acc = 0;
        for (int k = 2 * threadIdx.x + 1; k < 20000; k += 2 * blockDim.x)
            acc |= rows[k];
        if (acc) atomicOr(&any, 1);
        __syncthreads();
        if (threadIdx.x == 0) g_is64 = any ? 0 : 1;
    }
}

__global__ void hist_kernel(const int* __restrict__ rows) {
    const int is64 = g_is64;
    int i = blockIdx.x * blockDim.x + threadIdx.x;
    int stride = gridDim.x * blockDim.x;
    for (; i < N_EDGES; i += stride) atomicAdd(&g_counts[load_idx(rows, i, is64)], 1);
}

// --- scan: phase1 (block sums), fused phase2+3 (row_ptr, cursor) ---
#define SCAN_BLOCKS 196          // 196*256 = 50176 >= N_NODES
__global__ void scan_phase1() {
    __shared__ int sm[256];
    int i = blockIdx.x * 256 + threadIdx.x;
    int v = (i < N_NODES) ? g_counts[i] : 0;
    sm[threadIdx.x] = v;
    __syncthreads();
    for (int off = 128; off > 0; off >>= 1) {
        if (threadIdx.x < off) sm[threadIdx.x] += sm[threadIdx.x + off];
        __syncthreads();
    }
    if (threadIdx.x == 0) g_bsum[blockIdx.x] = sm[0];
}

// Each block redundantly scans the 196 block sums (shared barrier loop with
// its own 256-count scan), then writes row_ptr/cursor with its block offset.
__global__ void scan_phase23() {
    __shared__ int sb[256];
    __shared__ int sm[256];
    const int t = threadIdx.x;
    const int i = blockIdx.x * 256 + t;
    sb[t] = (t < SCAN_BLOCKS) ? g_bsum[t] : 0;
    int v = (i < N_NODES) ? g_counts[i] : 0;
    sm[t] = v;
    __syncthreads();
    for (int off = 1; off < 256; off <<= 1) {
        int u1 = (t >= off) ? sb[t - off] : 0;
        int u2 = (t >= off) ? sm[t - off] : 0;
        __syncthreads();
        sb[t] += u1;
        sm[t] += u2;
        __syncthreads();
    }
    if (i < N_NODES) {
        int excl_blk = (blockIdx.x > 0) ? sb[blockIdx.x - 1] : 0;   // inclusive->exclusive
        int p = excl_blk + sm[t] - v;
        g_row_ptr[i] = p;
        g_cursor[i]  = p;
    }
    if (blockIdx.x == 0 && t == 0) g_row_ptr[N_NODES] = N_EDGES;
}

// ---------------- fused scatter + GEMM (independent work, one launch) ----
// blocks [0, GEMM_BLOCKS): Y = H @ W  (fp32 + fp16 shadow)
// blocks [GEMM_BLOCKS, +SCATTER_BLOCKS): CSR scatter of edges
#define GEMM_RPB 16
#define GEMM_BLOCKS (N_NODES / GEMM_RPB)     // 3125
#define SCATTER_BLOCKS 1024
__global__ __launch_bounds__(384) void scatter_gemm_kernel(
        const int* __restrict__ rows, const int* __restrict__ cols,
        const float* __restrict__ vals,
        const float* __restrict__ H, const float* __restrict__ W) {
    if (blockIdx.x < GEMM_BLOCKS) {
        __shared__ float Ws[D * D];
        __shared__ float Hs[GEMM_RPB][D];
        const int tid = threadIdx.x;
        for (int i = tid; i < D * D; i += 384) Ws[i] = W[i];
        const int row0 = blockIdx.x * GEMM_RPB;
        for (int i = tid; i < GEMM_RPB * D; i += 384) {
            int r = i / D, c = i % D;
            Hs[r][c] = H[(row0 + r) * D + c];
        }
        __syncthreads();
        const int j = tid % 96;
        const int rbase = (tid / 96) * 4;
        float acc0 = 0.f, acc1 = 0.f, acc2 = 0.f, acc3 = 0.f;
        #pragma unroll 8
        for (int k = 0; k < D; k++) {
            float w = Ws[k * D + j];
            acc0 = fmaf(Hs[rbase + 0][k], w, acc0);
            acc1 = fmaf(Hs[rbase + 1][k], w, acc1);
            acc2 = fmaf(Hs[rbase + 2][k], w, acc2);
            acc3 = fmaf(Hs[rbase + 3][k], w, acc3);
        }
        float accs[4] = {acc0, acc1, acc2, acc3};
        float*  Yf = (float*)g_Y;              // device-side symbol refs: valid
        __half* Yh = (__half*)g_Yh;
        #pragma unroll
        for (int i = 0; i < 4; i++) {
            int r = row0 + rbase + i;
            Yf[r * D + j] = accs[i];
            Yh[r * D + j] = __float2half_rn(accs[i]);
        }
    } else {
        const int is64 = g_is64;
        int i = (blockIdx.x - GEMM_BLOCKS) * blockDim.x + threadIdx.x;
        int stride = SCATTER_BLOCKS * blockDim.x;
        for (; i < N_EDGES; i += stride) {
            int r = load_idx(rows, i, is64);
            int pos = atomicAdd(&g_cursor[r], 1);
            g_edges[pos] = make_int2(load_idx(cols, i, is64), __float_as_int(vals[i]));
        }
    }
}

// ---------------- SpMM + Chebyshev combine -----------------
// One warp per row; lanes 0..23 own 4 features each.
// Gather uses fp16 shadow Xh (192 B/row); linear terms use fp32 X, P.
// O[r] = a*S(X)[r] + b*X[r] + c*P[r] (+ bias);  Oh = fp16(O) if non-null.
__global__ __launch_bounds__(256) void spmm_kernel(const uint2*  __restrict__ Xh,
                                                   const float4* __restrict__ X,
                                                   const float4* __restrict__ P,
                                                   float4* __restrict__ O,
                                                   uint2*  __restrict__ Oh,
                                                   const float4* __restrict__ bias,
                                                   float a, float b, float c) {
    const int w = (blockIdx.x * blockDim.x + threadIdx.x) >> 5;
    if (w >= N_NODES) return;
    const int lane = threadIdx.x & 31;
    if (lane >= D4) return;
    const int start = g_row_ptr[w];
    const int end   = g_row_ptr[w + 1];

    float ax = 0.f, ay = 0.f, az = 0.f, aw = 0.f;
    #pragma unroll 4
    for (int e = start; e < end; ++e) {
        int2 ed = g_edges[e];                      // warp-uniform broadcast
        float v = __int_as_float(ed.y);
        uint2 h = __ldg(&Xh[ed.x * D4 + lane]);    // 4 halves, 8 B
        float2 f01 = __half22float2(*(const half2*)&h.x);
        float2 f23 = __half22float2(*(const half2*)&h.y);
        ax = fmaf(v, f01.x, ax);
        ay = fmaf(v, f01.y, ay);
        az = fmaf(v, f23.x, az);
        aw = fmaf(v, f23.y, aw);
    }

    const int base = w * D4 + lane;
    float4 xs = X[base];
    float4 t;
    t.x = a * ax + b * xs.x;
    t.y = a * ay + b * xs.y;
    t.z = a * az + b * xs.z;
    t.w = a * aw + b * xs.w;
    if (P) {
        float4 p = P[base];
        t.x += c * p.x; t.y += c * p.y; t.z += c * p.z; t.w += c * p.w;
    }
    if (bias) {
        float4 bv = bias[lane];
        t.x += bv.x; t.y += bv.y; t.z += bv.z; t.w += bv.w;
    }
    O[base] = t;
    if (Oh) {
        uint2 hh;
        *(half2*)&hh.x = __floats2half2_rn(t.x, t.y);
        *(half2*)&hh.y = __floats2half2_rn(t.z, t.w);
        Oh[base] = hh;
    }
}

// ---------------- launch ----------------
extern "C" void kernel_launch(void* const* d_in, const int* in_sizes, int n_in,
                              void* d_out, int out_size) {
    const int*   rows = (const int*)  d_in[0];
    const int*   cols = (const int*)  d_in[1];
    const float* vals = (const float*)d_in[2];
    const float* H    = (const float*)d_in[3];
    const float* W    = (const float*)d_in[4];
    const float* bias = (const float*)d_in[5];
    float* out = (float*)d_out;

    // Real DEVICE addresses (host-side symbol names are shadow addresses).
    float4 *Yp = nullptr, *T1p = nullptr, *T2p = nullptr;
    uint2  *Yhp = nullptr, *T1hp = nullptr, *T2hp = nullptr;
    cudaGetSymbolAddress((void**)&Yp,   g_Y);
    cudaGetSymbolAddress((void**)&T1p,  g_T1);
    cudaGetSymbolAddress((void**)&T2p,  g_T2);
    cudaGetSymbolAddress((void**)&Yhp,  g_Yh);
    cudaGetSymbolAddress((void**)&T1hp, g_T1h);
    cudaGetSymbolAddress((void**)&T2hp, g_T2h);

    // CSR build + GEMM (every call — no caching)
    zero_detect_kernel<<<256, 256>>>(rows);
    hist_kernel<<<1024, 256>>>(rows);
    scan_phase1<<<SCAN_BLOCKS, 256>>>();
    scan_phase23<<<SCAN_BLOCKS, 256>>>();
    scatter_gemm_kernel<<<GEMM_BLOCKS + SCATTER_BLOCKS, 384>>>(rows, cols, vals, H, W);

    const int SPMM_BLOCKS = (N_NODES * 32 + 255) / 256;
    float4* out4 = (float4*)out;
    const float4* bias4 = (const float4*)bias;
    // T1 = 2*S(Y) - Y
    spmm_kernel<<<SPMM_BLOCKS, 256>>>(Yhp,  Yp,  nullptr, T1p, T1hp, nullptr, 2.f, -1.f, 0.f);
    // T2 = 4*S(T1) - 2*T1 - Y
    spmm_kernel<<<SPMM_BLOCKS, 256>>>(T1hp, T1p, Yp,      T2p, T2hp, nullptr, 4.f, -2.f, -1.f);
    // out = Y + T1 + T2 + T3 + bias == 4*S(T2) - T2 + Y + bias  (T1 cancels)
    spmm_kernel<<<SPMM_BLOCKS, 256>>>(T2hp, T2p, Yp,      out4, nullptr, bias4, 4.f, -1.f, 1.f);
}